// round 15
// baseline (speedup 1.0000x reference)
#include <cuda_runtime.h>
#include <cuda_bf16.h>
#include <mma.h>
#include <math.h>

using namespace nvcuda;

#define G 1024
#define NNODE 256
#define FIN 128
#define DH 256
#define MAXD 128

// ---------------- scratch (device globals; no allocations allowed) -------------
__device__ float g_norm0[G * NNODE];
__device__ unsigned char g_cols[(long)G * NNODE * MAXD];
__device__ int   g_cnt [G * NNODE];
__device__ __nv_bfloat16 g_Yh[(long)G * NNODE * FIN];
__device__ __nv_bfloat16 g_Yl[(long)G * NNODE * FIN];
__device__ __nv_bfloat16 g_W0h[FIN * DH];
__device__ __nv_bfloat16 g_W0l[FIN * DH];
__device__ __nv_bfloat16 g_W1h[DH * DH];
__device__ __nv_bfloat16 g_W1l[DH * DH];
__device__ __nv_bfloat16 g_W2h[DH * DH];
__device__ __nv_bfloat16 g_W2l[DH * DH];
__device__ float g_X1 [G * NNODE * DH];
__device__ float g_spre[2 * G * NNODE];
__device__ __nv_bfloat16 g_Xp1h[(long)G * 32 * DH];
__device__ __nv_bfloat16 g_Xp1l[(long)G * 32 * DH];
__device__ float g_A1 [G * 32 * 32];
__device__ float g_norm1[G * 32];
__device__ float g_H1 [G * 32 * DH];
__device__ __nv_bfloat16 g_Xp2h[(long)G * 16 * DH];
__device__ __nv_bfloat16 g_Xp2l[(long)G * 16 * DH];
__device__ float g_A2 [G * 16 * 16];
__device__ float g_norm2[G * 16];
__device__ float g_H2 [G * 16 * DH];
__device__ float g_read[G * 1536];

// ---------------- cp.async helpers ---------------------------------------------
__device__ __forceinline__ void cp_async16(unsigned saddr, const void* gptr) {
    asm volatile("cp.async.cg.shared.global [%0], [%1], 16;" :: "r"(saddr), "l"(gptr));
}

// ---------------- build sparse adjacency lists + degree norm -------------------
__global__ void build_adj_kernel(const float* __restrict__ adj,
                                 unsigned char* __restrict__ cols,
                                 int* __restrict__ cnt, float* __restrict__ nrm)
{
    int row  = blockIdx.x * 8 + (threadIdx.x >> 5);
    int lane = threadIdx.x & 31;
    const float* a = adj + (long)row * 256;
    unsigned char* lst = cols + (long)row * MAXD;
    int base = 0;
#pragma unroll
    for (int c = 0; c < 8; c++) {
        float v = a[c * 32 + lane];
        unsigned m = __ballot_sync(0xffffffffu, v != 0.f);
        if (v != 0.f) {
            int pos = base + __popc(m & ((1u << lane) - 1));
            if (pos < MAXD) lst[pos] = (unsigned char)(c * 32 + lane);
        }
        base += __popc(m);
    }
    if (lane == 0) {
        cnt[row] = (base > MAXD) ? MAXD : base;
        nrm[row] = rsqrtf(fmaxf((float)base, 1.f));
    }
}

// ---------------- split W0+W1+W2 into bf16 hi/lo (one launch) ------------------
__global__ void split_all_w_kernel(const float* __restrict__ W0,
                                   const float* __restrict__ W1,
                                   const float* __restrict__ W2,
                                   __nv_bfloat16* __restrict__ W0h, __nv_bfloat16* __restrict__ W0l,
                                   __nv_bfloat16* __restrict__ W1h, __nv_bfloat16* __restrict__ W1l,
                                   __nv_bfloat16* __restrict__ W2h, __nv_bfloat16* __restrict__ W2l)
{
    int i = blockIdx.x * 256 + threadIdx.x;   // [0, 163840)
    const float* W; __nv_bfloat16 *Wh, *Wl; int idx;
    if (i < 32768)       { W = W0; Wh = W0h; Wl = W0l; idx = i; }
    else if (i < 98304)  { W = W1; Wh = W1h; Wl = W1l; idx = i - 32768; }
    else                 { W = W2; Wh = W2h; Wl = W2l; idx = i - 98304; }
    float v = W[idx];
    __nv_bfloat16 h = __float2bfloat16_rn(v);
    Wh[idx] = h;
    Wl[idx] = __float2bfloat16_rn(v - __bfloat162float(h));
}

// ------- layer-0 sparse aggregation, 64-col halves (2 CTA/SM); bf16 hi/lo out --
__global__ void spmm_feat_kernel(const unsigned char* __restrict__ cols,
                                 const int* __restrict__ cnt,
                                 const float* __restrict__ feat,
                                 const float* __restrict__ nrm,
                                 __nv_bfloat16* __restrict__ Yh,
                                 __nv_bfloat16* __restrict__ Yl)
{
    extern __shared__ float sX[];                 // [256][64] = 64 KB
    __shared__ float snrm[256];
    __shared__ int   scnt[256];

    int g = blockIdx.y, half = blockIdx.x;
    int tid = threadIdx.x;
    snrm[tid] = nrm[g * 256 + tid];
    scnt[tid] = cnt[g * 256 + tid];
    __syncthreads();

    {
        const float4* F = (const float4*)(feat + (long)g * 32768 + half * 64);
        float4* s4 = (float4*)sX;
        for (int t = tid; t < 4096; t += 256) {
            int r = t >> 4, c4 = t & 15;
            float4 v = F[(long)r * 32 + c4];
            float s = snrm[r];
            v.x *= s; v.y *= s; v.z *= s; v.w *= s;
            s4[r * 16 + c4] = v;
        }
    }
    __syncthreads();

    int lane = tid & 31, warp = tid >> 5;
    for (int i = warp; i < 256; i += 8) {
        int d = scnt[i];
        const unsigned char* lst = cols + ((long)g * 256 + i) * MAXD;
        float a0 = 0.f, a1 = 0.f;
        int k = 0;
        for (; k + 4 <= d; k += 4) {
            unsigned w = *(const unsigned*)(lst + k);   // warp-uniform -> broadcast
            int j0 = w & 255, j1 = (w >> 8) & 255, j2 = (w >> 16) & 255, j3 = w >> 24;
            float2 h0 = *(const float2*)(sX + j0 * 64 + lane * 2);
            float2 h1 = *(const float2*)(sX + j1 * 64 + lane * 2);
            float2 h2 = *(const float2*)(sX + j2 * 64 + lane * 2);
            float2 h3 = *(const float2*)(sX + j3 * 64 + lane * 2);
            a0 += h0.x + h1.x + h2.x + h3.x;
            a1 += h0.y + h1.y + h2.y + h3.y;
        }
        for (; k < d; k++) {
            int j = lst[k];
            float2 h = *(const float2*)(sX + j * 64 + lane * 2);
            a0 += h.x; a1 += h.y;
        }
        float nr = snrm[i];
        float o0 = a0 * nr, o1 = a1 * nr;
        __nv_bfloat16 h0 = __float2bfloat16_rn(o0);
        __nv_bfloat16 h1 = __float2bfloat16_rn(o1);
        long base = (long)g * 32768 + (long)i * 128 + half * 64 + lane * 2;
        *(__nv_bfloat162*)(Yh + base) = __nv_bfloat162(h0, h1);
        *(__nv_bfloat162*)(Yl + base) = __nv_bfloat162(
            __float2bfloat16_rn(o0 - __bfloat162float(h0)),
            __float2bfloat16_rn(o1 - __bfloat162float(h1)));
    }
}

// ===== generalized bf16 wmma 3-chain GEMM, cp.async double-buffered ============
#define WAL 56
#define WBL 136
#define WCL 132
#define STG_B 46080
#define STG_E 23040

template <int EPI>
__global__ void __launch_bounds__(256, 2) wmma_gen_kernel(
    const __nv_bfloat16* __restrict__ Ah, const __nv_bfloat16* __restrict__ Al,
    const __nv_bfloat16* __restrict__ Bh, const __nv_bfloat16* __restrict__ Bl,
    const float* __restrict__ bias, const float* __restrict__ Wsp,
    float* __restrict__ C, float* __restrict__ spreOut, int M, int K)
{
    extern __shared__ char smem[];
    __nv_bfloat16* sb = (__nv_bfloat16*)smem;
    float* sC = (float*)smem;
    unsigned sb32 = (unsigned)__cvta_generic_to_shared(smem);

    int tid = threadIdx.x, warp = tid >> 5;
    int bm = blockIdx.y * 128, bn = blockIdx.x * 128;
    int wm = warp >> 2, wn = warp & 3;

    wmma::fragment<wmma::accumulator, 16, 16, 16, float> acc[4][2];
#pragma unroll
    for (int i = 0; i < 4; i++)
#pragma unroll
        for (int j = 0; j < 2; j++) wmma::fill_fragment(acc[i][j], 0.f);

    auto issue_tile = [&](int k0, int buf) {
        unsigned base = sb32 + buf * STG_B;
#pragma unroll
        for (int it = 0; it < 2; it++) {
            int idx = tid + it * 256;
            int r = idx >> 2, c8 = (idx & 3) * 8;
            long gofs = (long)(bm + r) * K + k0 + c8;
            unsigned aoff = (unsigned)(r * WAL + c8) * 2;
            cp_async16(base + aoff, Ah + gofs);
            cp_async16(base + 14336 + aoff, Al + gofs);
        }
#pragma unroll
        for (int it = 0; it < 2; it++) {
            int idx = tid + it * 256;
            int r = idx >> 4, c8 = (idx & 15) * 8;
            long gofs = (long)(k0 + r) * 256 + bn + c8;
            unsigned boff = (unsigned)(r * WBL + c8) * 2;
            cp_async16(base + 28672 + boff, Bh + gofs);
            cp_async16(base + 37376 + boff, Bl + gofs);
        }
        asm volatile("cp.async.commit_group;" ::: "memory");
    };

    int NT = K >> 5;
    issue_tile(0, 0);

    for (int k = 0; k < NT; k++) {
        if (k < NT - 1) {
            issue_tile((k + 1) * 32, (k + 1) & 1);
            asm volatile("cp.async.wait_group 1;" ::: "memory");
        } else {
            asm volatile("cp.async.wait_group 0;" ::: "memory");
        }
        __syncthreads();

        __nv_bfloat16* sAh = sb + (k & 1) * STG_E;
        __nv_bfloat16* sAl = sAh + 7168;
        __nv_bfloat16* sBh = sAh + 14336;
        __nv_bfloat16* sBl = sAh + 18688;

#pragma unroll
        for (int kk = 0; kk < 32; kk += 16) {
            wmma::fragment<wmma::matrix_b, 16, 16, 16, __nv_bfloat16, wmma::row_major> bh[2], bl[2];
#pragma unroll
            for (int j = 0; j < 2; j++) {
                wmma::load_matrix_sync(bh[j], sBh + kk * WBL + wn * 32 + j * 16, WBL);
                wmma::load_matrix_sync(bl[j], sBl + kk * WBL + wn * 32 + j * 16, WBL);
            }
#pragma unroll
            for (int i = 0; i < 4; i++) {
                wmma::fragment<wmma::matrix_a, 16, 16, 16, __nv_bfloat16, wmma::row_major> ah, al;
                wmma::load_matrix_sync(ah, sAh + (wm * 64 + i * 16) * WAL + kk, WAL);
                wmma::load_matrix_sync(al, sAl + (wm * 64 + i * 16) * WAL + kk, WAL);
#pragma unroll
                for (int j = 0; j < 2; j++) {
                    wmma::mma_sync(acc[i][j], ah, bh[j], acc[i][j]);
                    wmma::mma_sync(acc[i][j], ah, bl[j], acc[i][j]);
                    wmma::mma_sync(acc[i][j], al, bh[j], acc[i][j]);
                }
            }
        }
        __syncthreads();
    }

    // stage C through smem — padded stride WCL
#pragma unroll
    for (int i = 0; i < 4; i++)
#pragma unroll
        for (int j = 0; j < 2; j++)
            wmma::store_matrix_sync(sC + (wm * 64 + i * 16) * WCL + wn * 32 + j * 16,
                                    acc[i][j], WCL, wmma::mem_row_major);
    __syncthreads();

    {
        int row = tid >> 1, half = tid & 1;
        int gRow = bm + row;
        float rd = 0.f;
        float* dst = C + (long)gRow * 256 + bn + half * 64;
#pragma unroll
        for (int c4 = 0; c4 < 16; c4++) {
            int col = half * 64 + c4 * 4;
            float4 v = *(float4*)(sC + row * WCL + col);
            if (EPI) {
                float4 bv = *(const float4*)(bias + bn + col);
                v.x += bv.x; v.y += bv.y; v.z += bv.z; v.w += bv.w;
                v.x = (v.x > 0.f) ? v.x : 0.01f * v.x;
                v.y = (v.y > 0.f) ? v.y : 0.01f * v.y;
                v.z = (v.z > 0.f) ? v.z : 0.01f * v.z;
                v.w = (v.w > 0.f) ? v.w : 0.01f * v.w;
                float4 wv = *(const float4*)(Wsp + bn + col);
                rd += v.x * wv.x + v.y * wv.y + v.z * wv.z + v.w * wv.w;
            }
            *(float4*)(dst + c4 * 4) = v;
        }
        if (EPI) {
            rd += __shfl_xor_sync(0xffffffffu, rd, 1);
            if (half == 0) spreOut[(long)blockIdx.x * M + gRow] = rd;
        }
    }
}

// ---------------- layer-0 SAGPool; induced subgraph via neighbor lists ---------
template <int NV, int KK>
__global__ void pool_kernel(const float* __restrict__ X, const float* __restrict__ A,
                            const float* __restrict__ nrm,
                            const float* __restrict__ Ws, const float* __restrict__ bs,
                            const unsigned char* __restrict__ colsL,
                            const int* __restrict__ cntL,
                            const float* __restrict__ spreParts,
                            __nv_bfloat16* __restrict__ Xph,
                            __nv_bfloat16* __restrict__ Xpl,
                            float* __restrict__ Aout,
                            float* __restrict__ normOut, float* __restrict__ readout,
                            int roff)
{
    int g = blockIdx.x;
    const float* Xg = X + (long)g * NV * 256;
    const float* ng = nrm + (long)g * NV;

    __shared__ float spre[NV];
    __shared__ float ssc[NV];
    __shared__ int   sidx[NV];
    __shared__ float sAn[KK * KK];
    __shared__ float snrm2[KK];
    __shared__ signed char srank[NV];

    int tid = threadIdx.x, lane = tid & 31, warp = tid >> 5;

    if (tid < NV)
        spre[tid] = (spreParts[(long)g * NV + tid] +
                     spreParts[(long)G * NNODE + (long)g * NV + tid]) * ng[tid];
    __syncthreads();

    float bsv = bs[0];
    for (int r = warp; r < NV; r += 8) {
        int d = cntL[g * NV + r];
        const unsigned char* lst = colsL + ((long)g * NV + r) * MAXD;
        float acc = 0.f;
        for (int q = lane; q < d; q += 32) acc += spre[lst[q]];
#pragma unroll
        for (int s = 16; s > 0; s >>= 1) acc += __shfl_down_sync(0xffffffffu, acc, s);
        if (lane == 0) { ssc[r] = ng[r] * acc + bsv; sidx[r] = r; }
    }
    __syncthreads();

    for (int ksz = 2; ksz <= NV; ksz <<= 1) {
        for (int j = ksz >> 1; j > 0; j >>= 1) {
            if (tid < NV) {
                int ixj = tid ^ j;
                if (ixj > tid) {
                    float s1 = ssc[tid], s2 = ssc[ixj];
                    int i1 = sidx[tid], i2 = sidx[ixj];
                    bool firstWorse = (s1 < s2) || (s1 == s2 && i1 > i2);
                    bool descRegion = ((tid & ksz) == 0);
                    bool doSwap = descRegion ? firstWorse : !firstWorse;
                    if (doSwap) {
                        ssc[tid] = s2; ssc[ixj] = s1;
                        sidx[tid] = i2; sidx[ixj] = i1;
                    }
                }
            }
            __syncthreads();
        }
    }

    // induced sub-adjacency from neighbor lists (coalesced) + next norm
    {
        if (tid < NV) srank[tid] = -1;
        for (int t = tid; t < KK * KK; t += 256) sAn[t] = 0.f;
        __syncthreads();
        if (tid < KK) srank[sidx[tid]] = (signed char)tid;
        __syncthreads();
        for (int r = warp; r < KK; r += 8) {
            int row = sidx[r];
            int d = cntL[g * NV + row];
            const unsigned char* lst = colsL + ((long)g * NV + row) * MAXD;
            for (int q = lane; q < d; q += 32) {
                int t = srank[lst[q]];
                if (t >= 0) sAn[r * KK + t] = 1.f;
            }
        }
        __syncthreads();
        for (int t = tid; t < KK * KK; t += 256) Aout[(long)g * KK * KK + t] = sAn[t];
        if (tid < KK) {
            float d = 0.f;
#pragma unroll
            for (int c = 0; c < KK; c++) d += sAn[tid * KK + c];
            float nv = rsqrtf(fmaxf(d, 1.f));
            normOut[(long)g * KK + tid] = nv;
            snrm2[tid] = nv;
        }
    }
    __syncthreads();

    if (tid < KK) ssc[tid] = tanhf(ssc[tid]);
    __syncthreads();

    {
        int j = tid;
        float csum = 0.f, cmax = -3.402823466e38f;
#pragma unroll 4
        for (int r = 0; r < KK; r++) {
            int row = sidx[r];
            float v = Xg[(long)row * 256 + j] * ssc[r];
            csum += v;
            cmax = fmaxf(cmax, v);
            float vs = v * snrm2[r];
            __nv_bfloat16 h = __float2bfloat16_rn(vs);
            long o = (long)g * KK * 256 + (long)r * 256 + j;
            Xph[o] = h;
            Xpl[o] = __float2bfloat16_rn(vs - __bfloat162float(h));
        }
        readout[(long)g * 1536 + roff + j] = csum;
        readout[(long)g * 1536 + roff + 256 + j] = cmax;
    }
}

// ====== fused conv + SAGPool for small layers ==================================
template <int NN, int KK, int EMIT>
__global__ void fused_conv_pool_kernel(const float* __restrict__ A,
                                       const float* __restrict__ H,
                                       const float* __restrict__ nrm,
                                       const float* __restrict__ bias,
                                       const float* __restrict__ Ws,
                                       const float* __restrict__ bs,
                                       __nv_bfloat16* __restrict__ Xph,
                                       __nv_bfloat16* __restrict__ Xpl,
                                       float* __restrict__ Aout,
                                       float* __restrict__ normOut,
                                       float* __restrict__ readout, int roff)
{
    extern __shared__ float sm[];
    float* sH   = sm;                    // NN*256
    float* sX   = sH + NN * 256;         // NN*256
    float* sAdj = sX + NN * 256;         // NN*NN
    float* sWs  = sAdj + NN * NN;        // 256

    __shared__ float snrm[NN];
    __shared__ float spre[NN];
    __shared__ float ssc[NN];
    __shared__ int   sidx[NN];
    __shared__ float sAn[KK * KK];
    __shared__ float snrm2[KK];

    int g = blockIdx.x;
    int tid = threadIdx.x, lane = tid & 31, warp = tid >> 5;

    sWs[tid] = Ws[tid];
    if (tid < NN) snrm[tid] = nrm[(long)g * NN + tid];
    for (int t = tid; t < NN * NN; t += 256) sAdj[t] = A[(long)g * NN * NN + t];
    {
        const float4* Hg = (const float4*)(H + (long)g * NN * 256);
        float4* s4 = (float4*)sH;
        for (int t = tid; t < NN * 64; t += 256) s4[t] = Hg[t];
    }
    __syncthreads();

    {
        float bj = bias[tid];
#pragma unroll 4
        for (int i = 0; i < NN; i++) {
            float acc = 0.f;
#pragma unroll
            for (int k = 0; k < NN; k++) acc += sAdj[i * NN + k] * sH[k * 256 + tid];
            float v = acc * snrm[i] + bj;
            sX[i * 256 + tid] = (v > 0.f) ? v : 0.01f * v;
        }
    }
    __syncthreads();

    for (int r = warp; r < NN; r += 8) {
        float acc = 0.f;
#pragma unroll
        for (int q = lane; q < 256; q += 32) acc += sX[r * 256 + q] * sWs[q];
#pragma unroll
        for (int s = 16; s > 0; s >>= 1) acc += __shfl_down_sync(0xffffffffu, acc, s);
        if (lane == 0) spre[r] = snrm[r] * acc;
    }
    __syncthreads();

    if (tid < NN) {
        float acc = 0.f;
#pragma unroll
        for (int q = 0; q < NN; q++) acc += sAdj[tid * NN + q] * spre[q];
        ssc[tid] = snrm[tid] * acc + bs[0];
        sidx[tid] = tid;
    }
    __syncthreads();

    for (int ksz = 2; ksz <= NN; ksz <<= 1) {
        for (int j = ksz >> 1; j > 0; j >>= 1) {
            if (tid < NN) {
                int ixj = tid ^ j;
                if (ixj > tid) {
                    float s1 = ssc[tid], s2 = ssc[ixj];
                    int i1 = sidx[tid], i2 = sidx[ixj];
                    bool firstWorse = (s1 < s2) || (s1 == s2 && i1 > i2);
                    bool descRegion = ((tid & ksz) == 0);
                    bool doSwap = descRegion ? firstWorse : !firstWorse;
                    if (doSwap) {
                        ssc[tid] = s2; ssc[ixj] = s1;
                        sidx[tid] = i2; sidx[ixj] = i1;
                    }
                }
            }
            __syncthreads();
        }
    }

    if (EMIT) {
        for (int t = tid; t < KK * KK; t += 256) {
            int r = t / KK, c = t % KK;
            sAn[t] = sAdj[sidx[r] * NN + sidx[c]];
        }
        __syncthreads();
        for (int t = tid; t < KK * KK; t += 256) Aout[(long)g * KK * KK + t] = sAn[t];
        if (tid < KK) {
            float d = 0.f;
#pragma unroll
            for (int c = 0; c < KK; c++) d += sAn[tid * KK + c];
            float nv = rsqrtf(fmaxf(d, 1.f));
            normOut[(long)g * KK + tid] = nv;
            snrm2[tid] = nv;
        }
        __syncthreads();
    }

    if (tid < KK) ssc[tid] = tanhf(ssc[tid]);
    __syncthreads();

    {
        int j = tid;
        float csum = 0.f, cmax = -3.402823466e38f;
#pragma unroll
        for (int r = 0; r < KK; r++) {
            int row = sidx[r];
            float v = sX[row * 256 + j] * ssc[r];
            csum += v;
            cmax = fmaxf(cmax, v);
            if (EMIT) {
                float vs = v * snrm2[r];
                __nv_bfloat16 h = __float2bfloat16_rn(vs);
                long o = (long)g * KK * 256 + (long)r * 256 + j;
                Xph[o] = h;
                Xpl[o] = __float2bfloat16_rn(vs - __bfloat162float(h));
            }
        }
        readout[(long)g * 1536 + roff + j] = csum;
        readout[(long)g * 1536 + roff + 256 + j] = cmax;
    }
}

// ====== fused MLP head (round-7 proven) ========================================
__global__ void __launch_bounds__(256) mlp_head_kernel(
    const float* __restrict__ read, const float* __restrict__ Wd1,
    const float* __restrict__ bd1, const float* __restrict__ Wd2,
    const float* __restrict__ bd2, float* __restrict__ out)
{
    extern __shared__ float sm[];
    float* sR = sm;
    float* sP = sm + 4 * 1536;
    float* sH = sP;

    int tid = threadIdx.x;
    int g0 = blockIdx.x * 4;
    int lane = tid & 31, kw = tid >> 5;

    {
        const float4* src = (const float4*)(read + (long)g0 * 1536);
        float4* d4 = (float4*)sR;
#pragma unroll
        for (int i = 0; i < 6; i++) d4[tid + i * 256] = src[tid + i * 256];
    }
    __syncthreads();

    float4 acc[4];
#pragma unroll
    for (int gg = 0; gg < 4; gg++) acc[gg] = make_float4(0.f, 0.f, 0.f, 0.f);
    {
        const float4* W14 = (const float4*)Wd1;
        int kbeg = kw * 192;
#pragma unroll 2
        for (int k = kbeg; k < kbeg + 192; k++) {
            float4 wd = __ldg(&W14[k * 32 + lane]);
#pragma unroll
            for (int gg = 0; gg < 4; gg++) {
                float rv = sR[gg * 1536 + k];
                acc[gg].x += rv * wd.x;
                acc[gg].y += rv * wd.y;
                acc[gg].z += rv * wd.z;
                acc[gg].w += rv * wd.w;
            }
        }
    }
#pragma unroll
    for (int gg = 0; gg < 4; gg++)
        ((float4*)sP)[(kw * 4 + gg) * 32 + lane] = acc[gg];
    __syncthreads();

#pragma unroll
    for (int rep = 0; rep < 2; rep++) {
        int idx = tid + rep * 256;
        int gg = idx >> 7, j = idx & 127;
        float s = 0.f;
#pragma unroll
        for (int w = 0; w < 8; w++) s += sP[(w * 4 + gg) * 128 + j];
        s += bd1[j];
        s = (s > 0.f) ? s : 0.01f * s;
        acc[0].x = s;
        __syncthreads();
        sH[gg * 128 + j] = acc[0].x;
        __syncthreads();
    }

    if (kw < 4) {
        float a0 = 0.f, a1 = 0.f;
#pragma unroll
        for (int c = 0; c < 4; c++) {
            int k = lane + c * 32;
            float h = sH[kw * 128 + k];
            a0 += h * Wd2[k * 2 + 0];
            a1 += h * Wd2[k * 2 + 1];
        }
#pragma unroll
        for (int s = 16; s > 0; s >>= 1) {
            a0 += __shfl_down_sync(0xffffffffu, a0, s);
            a1 += __shfl_down_sync(0xffffffffu, a1, s);
        }
        if (lane == 0) {
            out[(g0 + kw) * 2 + 0] = 1.f / (1.f + expf(-(a0 + bd2[0])));
            out[(g0 + kw) * 2 + 1] = 1.f / (1.f + expf(-(a1 + bd2[1])));
        }
    }
}

// --------------------------------- launch --------------------------------------
extern "C" void kernel_launch(void* const* d_in, const int* in_sizes, int n_in,
                              void* d_out, int out_size)
{
    const float* feat = (const float*)d_in[0];
    const float* adj  = (const float*)d_in[1];
    const float* W0   = (const float*)d_in[2];
    const float* b0   = (const float*)d_in[3];
    const float* Ws0  = (const float*)d_in[4];
    const float* bs0  = (const float*)d_in[5];
    const float* W1   = (const float*)d_in[6];
    const float* b1   = (const float*)d_in[7];
    const float* Ws1  = (const float*)d_in[8];
    const float* bs1  = (const float*)d_in[9];
    const float* W2   = (const float*)d_in[10];
    const float* b2   = (const float*)d_in[11];
    const float* Ws2  = (const float*)d_in[12];
    const float* bs2  = (const float*)d_in[13];
    const float* Wd1  = (const float*)d_in[14];
    const float* bd1  = (const float*)d_in[15];
    const float* Wd2  = (const float*)d_in[16];
    const float* bd2  = (const float*)d_in[17];
    float* out = (float*)d_out;

    float *p_norm0, *p_X1, *p_spre, *p_A1, *p_norm1, *p_H1;
    float *p_A2, *p_norm2, *p_H2, *p_read;
    unsigned char* p_cols; int* p_cnt;
    __nv_bfloat16 *p_Yh, *p_Yl, *p_W0h, *p_W0l, *p_W1h, *p_W1l, *p_W2h, *p_W2l;
    __nv_bfloat16 *p_Xp1h, *p_Xp1l, *p_Xp2h, *p_Xp2l;
    cudaGetSymbolAddress((void**)&p_norm0, g_norm0);
    cudaGetSymbolAddress((void**)&p_cols, g_cols);
    cudaGetSymbolAddress((void**)&p_cnt, g_cnt);
    cudaGetSymbolAddress((void**)&p_Yh, g_Yh);
    cudaGetSymbolAddress((void**)&p_Yl, g_Yl);
    cudaGetSymbolAddress((void**)&p_W0h, g_W0h);
    cudaGetSymbolAddress((void**)&p_W0l, g_W0l);
    cudaGetSymbolAddress((void**)&p_W1h, g_W1h);
    cudaGetSymbolAddress((void**)&p_W1l, g_W1l);
    cudaGetSymbolAddress((void**)&p_W2h, g_W2h);
    cudaGetSymbolAddress((void**)&p_W2l, g_W2l);
    cudaGetSymbolAddress((void**)&p_X1, g_X1);
    cudaGetSymbolAddress((void**)&p_spre, g_spre);
    cudaGetSymbolAddress((void**)&p_Xp1h, g_Xp1h);
    cudaGetSymbolAddress((void**)&p_Xp1l, g_Xp1l);
    cudaGetSymbolAddress((void**)&p_A1, g_A1);
    cudaGetSymbolAddress((void**)&p_norm1, g_norm1);
    cudaGetSymbolAddress((void**)&p_H1, g_H1);
    cudaGetSymbolAddress((void**)&p_Xp2h, g_Xp2h);
    cudaGetSymbolAddress((void**)&p_Xp2l, g_Xp2l);
    cudaGetSymbolAddress((void**)&p_A2, g_A2);
    cudaGetSymbolAddress((void**)&p_norm2, g_norm2);
    cudaGetSymbolAddress((void**)&p_H2, g_H2);
    cudaGetSymbolAddress((void**)&p_read, g_read);

    const int headSmem = (4 * 1536 + 8 * 4 * 128) * 4;
    const int wmmaSmem = 2 * STG_B;
    const int spmmSmem = 65536;
    const int fcp32Smem = (32 * 256 * 2 + 32 * 32 + 256) * 4;
    const int fcp16Smem = (16 * 256 * 2 + 16 * 16 + 256) * 4;
    cudaFuncSetAttribute(spmm_feat_kernel, cudaFuncAttributeMaxDynamicSharedMemorySize, spmmSmem);
    cudaFuncSetAttribute(mlp_head_kernel, cudaFuncAttributeMaxDynamicSharedMemorySize, headSmem);
    cudaFuncSetAttribute(wmma_gen_kernel<1>, cudaFuncAttributeMaxDynamicSharedMemorySize, wmmaSmem);
    cudaFuncSetAttribute(wmma_gen_kernel<0>, cudaFuncAttributeMaxDynamicSharedMemorySize, wmmaSmem);
    cudaFuncSetAttribute(fused_conv_pool_kernel<32, 16, 1>, cudaFuncAttributeMaxDynamicSharedMemorySize, fcp32Smem);
    cudaFuncSetAttribute(fused_conv_pool_kernel<16, 8, 0>, cudaFuncAttributeMaxDynamicSharedMemorySize, fcp16Smem);

    // ---- layer 0
    build_adj_kernel<<<G * NNODE / 8, 256>>>(adj, p_cols, p_cnt, p_norm0);
    split_all_w_kernel<<<640, 256>>>(W0, W1, W2, p_W0h, p_W0l, p_W1h, p_W1l,
                                     p_W2h, p_W2l);
    spmm_feat_kernel<<<dim3(2, G, 1), 256, spmmSmem>>>(p_cols, p_cnt, feat, p_norm0,
                                                       p_Yh, p_Yl);
    wmma_gen_kernel<1><<<dim3(2, 2048, 1), 256, wmmaSmem>>>(
        p_Yh, p_Yl, p_W0h, p_W0l, b0, Ws0, p_X1, p_spre, G * NNODE, FIN);
    pool_kernel<256, 32><<<G, 256>>>(p_X1, adj, p_norm0, Ws0, bs0, p_cols, p_cnt,
                                     p_spre, p_Xp1h, p_Xp1l, p_A1, p_norm1, p_read, 0);
    // ---- layer 1
    wmma_gen_kernel<0><<<dim3(2, 256, 1), 256, wmmaSmem>>>(
        p_Xp1h, p_Xp1l, p_W1h, p_W1l, nullptr, nullptr, p_H1, nullptr, G * 32, DH);
    fused_conv_pool_kernel<32, 16, 1><<<G, 256, fcp32Smem>>>(
        p_A1, p_H1, p_norm1, b1, Ws1, bs1, p_Xp2h, p_Xp2l, p_A2, p_norm2, p_read, 512);
    // ---- layer 2
    wmma_gen_kernel<0><<<dim3(2, 128, 1), 256, wmmaSmem>>>(
        p_Xp2h, p_Xp2l, p_W2h, p_W2l, nullptr, nullptr, p_H2, nullptr, G * 16, DH);
    fused_conv_pool_kernel<16, 8, 0><<<G, 256, fcp16Smem>>>(
        p_A2, p_H2, p_norm2, b2, Ws2, bs2, nullptr, nullptr, nullptr, nullptr, p_read, 1024);
    // ---- fused MLP head
    mlp_head_kernel<<<G / 4, 256, headSmem>>>(p_read, Wd1, bd1, Wd2, bd2, out);
}

// round 16
// speedup vs baseline: 1.0087x; 1.0087x over previous
#include <cuda_runtime.h>
#include <cuda_bf16.h>
#include <mma.h>
#include <math.h>

using namespace nvcuda;

#define G 1024
#define NNODE 256
#define FIN 128
#define DH 256
#define MAXD 128

// ---------------- scratch (device globals; no allocations allowed) -------------
__device__ float g_norm0[G * NNODE];
__device__ unsigned char g_cols[(long)G * NNODE * MAXD];
__device__ int   g_cnt [G * NNODE];
__device__ __nv_bfloat16 g_Yh[(long)G * NNODE * FIN];
__device__ __nv_bfloat16 g_Yl[(long)G * NNODE * FIN];
__device__ __nv_bfloat16 g_W0h[FIN * DH];
__device__ __nv_bfloat16 g_W0l[FIN * DH];
__device__ __nv_bfloat16 g_W1h[DH * DH];
__device__ __nv_bfloat16 g_W1l[DH * DH];
__device__ __nv_bfloat16 g_W2h[DH * DH];
__device__ __nv_bfloat16 g_W2l[DH * DH];
__device__ float g_X1 [G * NNODE * DH];
__device__ float g_spre[2 * G * NNODE];
__device__ __nv_bfloat16 g_Xp1h[(long)G * 32 * DH];
__device__ __nv_bfloat16 g_Xp1l[(long)G * 32 * DH];
__device__ float g_A1 [G * 32 * 32];
__device__ float g_norm1[G * 32];
__device__ float g_H1 [G * 32 * DH];
__device__ float g_X2 [G * 32 * DH];
__device__ __nv_bfloat16 g_Xp2h[(long)G * 16 * DH];
__device__ __nv_bfloat16 g_Xp2l[(long)G * 16 * DH];
__device__ float g_A2 [G * 16 * 16];
__device__ float g_norm2[G * 16];
__device__ float g_H2 [G * 16 * DH];
__device__ float g_X3 [G * 16 * DH];
__device__ float g_read[G * 1536];

// ---------------- cp.async helpers ---------------------------------------------
__device__ __forceinline__ void cp_async16(unsigned saddr, const void* gptr) {
    asm volatile("cp.async.cg.shared.global [%0], [%1], 16;" :: "r"(saddr), "l"(gptr));
}

// ---------------- build sparse adjacency lists + degree norm -------------------
__global__ void build_adj_kernel(const float* __restrict__ adj,
                                 unsigned char* __restrict__ cols,
                                 int* __restrict__ cnt, float* __restrict__ nrm)
{
    int row  = blockIdx.x * 8 + (threadIdx.x >> 5);
    int lane = threadIdx.x & 31;
    const float* a = adj + (long)row * 256;
    unsigned char* lst = cols + (long)row * MAXD;
    int base = 0;
#pragma unroll
    for (int c = 0; c < 8; c++) {
        float v = a[c * 32 + lane];
        unsigned m = __ballot_sync(0xffffffffu, v != 0.f);
        if (v != 0.f) {
            int pos = base + __popc(m & ((1u << lane) - 1));
            if (pos < MAXD) lst[pos] = (unsigned char)(c * 32 + lane);
        }
        base += __popc(m);
    }
    if (lane == 0) {
        cnt[row] = (base > MAXD) ? MAXD : base;
        nrm[row] = rsqrtf(fmaxf((float)base, 1.f));
    }
}

// ---------------- split W0+W1+W2 into bf16 hi/lo (one launch) ------------------
__global__ void split_all_w_kernel(const float* __restrict__ W0,
                                   const float* __restrict__ W1,
                                   const float* __restrict__ W2,
                                   __nv_bfloat16* __restrict__ W0h, __nv_bfloat16* __restrict__ W0l,
                                   __nv_bfloat16* __restrict__ W1h, __nv_bfloat16* __restrict__ W1l,
                                   __nv_bfloat16* __restrict__ W2h, __nv_bfloat16* __restrict__ W2l)
{
    int i = blockIdx.x * 256 + threadIdx.x;   // [0, 163840)
    const float* W; __nv_bfloat16 *Wh, *Wl; int idx;
    if (i < 32768)       { W = W0; Wh = W0h; Wl = W0l; idx = i; }
    else if (i < 98304)  { W = W1; Wh = W1h; Wl = W1l; idx = i - 32768; }
    else                 { W = W2; Wh = W2h; Wl = W2l; idx = i - 98304; }
    float v = W[idx];
    __nv_bfloat16 h = __float2bfloat16_rn(v);
    Wh[idx] = h;
    Wl[idx] = __float2bfloat16_rn(v - __bfloat162float(h));
}

// ------- layer-0 sparse aggregation, 64-col halves (2 CTA/SM); bf16 hi/lo out --
__global__ void spmm_feat_kernel(const unsigned char* __restrict__ cols,
                                 const int* __restrict__ cnt,
                                 const float* __restrict__ feat,
                                 const float* __restrict__ nrm,
                                 __nv_bfloat16* __restrict__ Yh,
                                 __nv_bfloat16* __restrict__ Yl)
{
    extern __shared__ float sX[];                 // [256][64] = 64 KB
    __shared__ float snrm[256];
    __shared__ int   scnt[256];

    int g = blockIdx.y, half = blockIdx.x;
    int tid = threadIdx.x;
    snrm[tid] = nrm[g * 256 + tid];
    scnt[tid] = cnt[g * 256 + tid];
    __syncthreads();

    {
        const float4* F = (const float4*)(feat + (long)g * 32768 + half * 64);
        float4* s4 = (float4*)sX;
        for (int t = tid; t < 4096; t += 256) {
            int r = t >> 4, c4 = t & 15;
            float4 v = F[(long)r * 32 + c4];
            float s = snrm[r];
            v.x *= s; v.y *= s; v.z *= s; v.w *= s;
            s4[r * 16 + c4] = v;
        }
    }
    __syncthreads();

    int lane = tid & 31, warp = tid >> 5;
    for (int i = warp; i < 256; i += 8) {
        int d = scnt[i];
        const unsigned char* lst = cols + ((long)g * 256 + i) * MAXD;
        float a0 = 0.f, a1 = 0.f;
        int k = 0;
        for (; k + 4 <= d; k += 4) {
            unsigned w = *(const unsigned*)(lst + k);   // warp-uniform -> broadcast
            int j0 = w & 255, j1 = (w >> 8) & 255, j2 = (w >> 16) & 255, j3 = w >> 24;
            float2 h0 = *(const float2*)(sX + j0 * 64 + lane * 2);
            float2 h1 = *(const float2*)(sX + j1 * 64 + lane * 2);
            float2 h2 = *(const float2*)(sX + j2 * 64 + lane * 2);
            float2 h3 = *(const float2*)(sX + j3 * 64 + lane * 2);
            a0 += h0.x + h1.x + h2.x + h3.x;
            a1 += h0.y + h1.y + h2.y + h3.y;
        }
        for (; k < d; k++) {
            int j = lst[k];
            float2 h = *(const float2*)(sX + j * 64 + lane * 2);
            a0 += h.x; a1 += h.y;
        }
        float nr = snrm[i];
        float o0 = a0 * nr, o1 = a1 * nr;
        __nv_bfloat16 h0 = __float2bfloat16_rn(o0);
        __nv_bfloat16 h1 = __float2bfloat16_rn(o1);
        long base = (long)g * 32768 + (long)i * 128 + half * 64 + lane * 2;
        *(__nv_bfloat162*)(Yh + base) = __nv_bfloat162(h0, h1);
        *(__nv_bfloat162*)(Yl + base) = __nv_bfloat162(
            __float2bfloat16_rn(o0 - __bfloat162float(h0)),
            __float2bfloat16_rn(o1 - __bfloat162float(h1)));
    }
}

// ===== generalized bf16 wmma 3-chain GEMM, cp.async double-buffered ============
#define WAL 56
#define WBL 136
#define WCL 132
#define STG_B 46080
#define STG_E 23040

template <int EPI>
__global__ void __launch_bounds__(256, 2) wmma_gen_kernel(
    const __nv_bfloat16* __restrict__ Ah, const __nv_bfloat16* __restrict__ Al,
    const __nv_bfloat16* __restrict__ Bh, const __nv_bfloat16* __restrict__ Bl,
    const float* __restrict__ bias, const float* __restrict__ Wsp,
    float* __restrict__ C, float* __restrict__ spreOut, int M, int K)
{
    extern __shared__ char smem[];
    __nv_bfloat16* sb = (__nv_bfloat16*)smem;
    float* sC = (float*)smem;
    unsigned sb32 = (unsigned)__cvta_generic_to_shared(smem);

    int tid = threadIdx.x, warp = tid >> 5;
    int bm = blockIdx.y * 128, bn = blockIdx.x * 128;
    int wm = warp >> 2, wn = warp & 3;

    wmma::fragment<wmma::accumulator, 16, 16, 16, float> acc[4][2];
#pragma unroll
    for (int i = 0; i < 4; i++)
#pragma unroll
        for (int j = 0; j < 2; j++) wmma::fill_fragment(acc[i][j], 0.f);

    auto issue_tile = [&](int k0, int buf) {
        unsigned base = sb32 + buf * STG_B;
#pragma unroll
        for (int it = 0; it < 2; it++) {
            int idx = tid + it * 256;
            int r = idx >> 2, c8 = (idx & 3) * 8;
            long gofs = (long)(bm + r) * K + k0 + c8;
            unsigned aoff = (unsigned)(r * WAL + c8) * 2;
            cp_async16(base + aoff, Ah + gofs);
            cp_async16(base + 14336 + aoff, Al + gofs);
        }
#pragma unroll
        for (int it = 0; it < 2; it++) {
            int idx = tid + it * 256;
            int r = idx >> 4, c8 = (idx & 15) * 8;
            long gofs = (long)(k0 + r) * 256 + bn + c8;
            unsigned boff = (unsigned)(r * WBL + c8) * 2;
            cp_async16(base + 28672 + boff, Bh + gofs);
            cp_async16(base + 37376 + boff, Bl + gofs);
        }
        asm volatile("cp.async.commit_group;" ::: "memory");
    };

    int NT = K >> 5;
    issue_tile(0, 0);

    for (int k = 0; k < NT; k++) {
        if (k < NT - 1) {
            issue_tile((k + 1) * 32, (k + 1) & 1);
            asm volatile("cp.async.wait_group 1;" ::: "memory");
        } else {
            asm volatile("cp.async.wait_group 0;" ::: "memory");
        }
        __syncthreads();

        __nv_bfloat16* sAh = sb + (k & 1) * STG_E;
        __nv_bfloat16* sAl = sAh + 7168;
        __nv_bfloat16* sBh = sAh + 14336;
        __nv_bfloat16* sBl = sAh + 18688;

#pragma unroll
        for (int kk = 0; kk < 32; kk += 16) {
            wmma::fragment<wmma::matrix_b, 16, 16, 16, __nv_bfloat16, wmma::row_major> bh[2], bl[2];
#pragma unroll
            for (int j = 0; j < 2; j++) {
                wmma::load_matrix_sync(bh[j], sBh + kk * WBL + wn * 32 + j * 16, WBL);
                wmma::load_matrix_sync(bl[j], sBl + kk * WBL + wn * 32 + j * 16, WBL);
            }
#pragma unroll
            for (int i = 0; i < 4; i++) {
                wmma::fragment<wmma::matrix_a, 16, 16, 16, __nv_bfloat16, wmma::row_major> ah, al;
                wmma::load_matrix_sync(ah, sAh + (wm * 64 + i * 16) * WAL + kk, WAL);
                wmma::load_matrix_sync(al, sAl + (wm * 64 + i * 16) * WAL + kk, WAL);
#pragma unroll
                for (int j = 0; j < 2; j++) {
                    wmma::mma_sync(acc[i][j], ah, bh[j], acc[i][j]);
                    wmma::mma_sync(acc[i][j], ah, bl[j], acc[i][j]);
                    wmma::mma_sync(acc[i][j], al, bh[j], acc[i][j]);
                }
            }
        }
        __syncthreads();
    }

    // stage C through smem — padded stride WCL
#pragma unroll
    for (int i = 0; i < 4; i++)
#pragma unroll
        for (int j = 0; j < 2; j++)
            wmma::store_matrix_sync(sC + (wm * 64 + i * 16) * WCL + wn * 32 + j * 16,
                                    acc[i][j], WCL, wmma::mem_row_major);
    __syncthreads();

    {
        int row = tid >> 1, half = tid & 1;
        int gRow = bm + row;
        float rd = 0.f;
        float* dst = C + (long)gRow * 256 + bn + half * 64;
#pragma unroll
        for (int c4 = 0; c4 < 16; c4++) {
            int col = half * 64 + c4 * 4;
            float4 v = *(float4*)(sC + row * WCL + col);
            if (EPI) {
                float4 bv = *(const float4*)(bias + bn + col);
                v.x += bv.x; v.y += bv.y; v.z += bv.z; v.w += bv.w;
                v.x = (v.x > 0.f) ? v.x : 0.01f * v.x;
                v.y = (v.y > 0.f) ? v.y : 0.01f * v.y;
                v.z = (v.z > 0.f) ? v.z : 0.01f * v.z;
                v.w = (v.w > 0.f) ? v.w : 0.01f * v.w;
                float4 wv = *(const float4*)(Wsp + bn + col);
                rd += v.x * wv.x + v.y * wv.y + v.z * wv.z + v.w * wv.w;
            }
            *(float4*)(dst + c4 * 4) = v;
        }
        if (EPI) {
            rd += __shfl_xor_sync(0xffffffffu, rd, 1);
            if (half == 0) spreOut[(long)blockIdx.x * M + gRow] = rd;
        }
    }
}

// ---------------- small batched conv: X = leaky(adj@H * norm + b) ---------------
template <int NN>
__global__ void conv_small_kernel(const float* __restrict__ A, const float* __restrict__ H,
                                  const float* __restrict__ nrm, const float* __restrict__ bias,
                                  float* __restrict__ X)
{
    int g = blockIdx.x;
    __shared__ float sAdj[NN][NN + 1];
    __shared__ float sH[NN][256];
    const float* Ag = A + (long)g * NN * NN;
    int tid = threadIdx.x;
    for (int t = tid; t < NN * NN; t += 256) sAdj[t / NN][t % NN] = Ag[t];
    {
        const float4* Hg4 = (const float4*)(H + (long)g * NN * 256);
        float4* s4 = (float4*)sH;
        for (int t = tid; t < NN * 64; t += 256) s4[t] = Hg4[t];
    }
    __syncthreads();
    int j = tid;
    float bj = bias[j];
#pragma unroll 4
    for (int i = 0; i < NN; i++) {
        float acc = 0.f;
#pragma unroll
        for (int k = 0; k < NN; k++) acc += sAdj[i][k] * sH[k][j];
        float v = acc * nrm[(long)g * NN + i] + bj;
        X[(long)g * NN * 256 + (long)i * 256 + j] = (v > 0.f) ? v : 0.01f * v;
    }
}

// ---------------- SAGPool: emits Xp as bf16 hi/lo with next norm folded --------
template <int NV, int KK>
__global__ void pool_kernel(const float* __restrict__ X, const float* __restrict__ A,
                            const float* __restrict__ nrm,
                            const float* __restrict__ Ws, const float* __restrict__ bs,
                            const unsigned char* __restrict__ colsL,
                            const int* __restrict__ cntL,
                            const float* __restrict__ spreParts,
                            __nv_bfloat16* __restrict__ Xph,
                            __nv_bfloat16* __restrict__ Xpl,
                            float* __restrict__ Aout,
                            float* __restrict__ normOut, float* __restrict__ readout,
                            int roff)
{
    int g = blockIdx.x;
    const float* Xg = X + (long)g * NV * 256;
    const float* Ag = A + (long)g * NV * NV;
    const float* ng = nrm + (long)g * NV;

    __shared__ float sWs[256];
    __shared__ float spre[NV];
    __shared__ float ssc[NV];
    __shared__ int   sidx[NV];
    __shared__ float sAn[KK * KK];
    __shared__ float snrm2[KK];

    int tid = threadIdx.x, lane = tid & 31, warp = tid >> 5;

    if (spreParts) {
        if (tid < NV)
            spre[tid] = (spreParts[(long)g * NV + tid] +
                         spreParts[(long)G * NNODE + (long)g * NV + tid]) * ng[tid];
        __syncthreads();
    } else {
        sWs[tid] = Ws[tid];
        __syncthreads();
        for (int r = warp; r < NV; r += 8) {
            float acc = 0.f;
            for (int q = lane; q < 256; q += 32) acc += Xg[(long)r * 256 + q] * sWs[q];
#pragma unroll
            for (int s = 16; s > 0; s >>= 1) acc += __shfl_down_sync(0xffffffffu, acc, s);
            if (lane == 0) spre[r] = ng[r] * acc;
        }
        __syncthreads();
    }

    float bsv = bs[0];
    if (colsL) {
        for (int r = warp; r < NV; r += 8) {
            int d = cntL[g * NV + r];
            const unsigned char* lst = colsL + ((long)g * NV + r) * MAXD;
            float acc = 0.f;
            for (int q = lane; q < d; q += 32) acc += spre[lst[q]];
#pragma unroll
            for (int s = 16; s > 0; s >>= 1) acc += __shfl_down_sync(0xffffffffu, acc, s);
            if (lane == 0) { ssc[r] = ng[r] * acc + bsv; sidx[r] = r; }
        }
    } else {
        for (int r = warp; r < NV; r += 8) {
            float acc = 0.f;
            for (int q = lane; q < NV; q += 32) acc += Ag[(long)r * NV + q] * spre[q];
#pragma unroll
            for (int s = 16; s > 0; s >>= 1) acc += __shfl_down_sync(0xffffffffu, acc, s);
            if (lane == 0) { ssc[r] = ng[r] * acc + bsv; sidx[r] = r; }
        }
    }
    __syncthreads();

    for (int ksz = 2; ksz <= NV; ksz <<= 1) {
        for (int j = ksz >> 1; j > 0; j >>= 1) {
            if (tid < NV) {
                int ixj = tid ^ j;
                if (ixj > tid) {
                    float s1 = ssc[tid], s2 = ssc[ixj];
                    int i1 = sidx[tid], i2 = sidx[ixj];
                    bool firstWorse = (s1 < s2) || (s1 == s2 && i1 > i2);
                    bool descRegion = ((tid & ksz) == 0);
                    bool doSwap = descRegion ? firstWorse : !firstWorse;
                    if (doSwap) {
                        ssc[tid] = s2; ssc[ixj] = s1;
                        sidx[tid] = i2; sidx[ixj] = i1;
                    }
                }
            }
            __syncthreads();
        }
    }

    if (Aout) {
        for (int t = tid; t < KK * KK; t += 256) {
            int r = t / KK, c = t % KK;
            sAn[t] = Ag[(long)sidx[r] * NV + sidx[c]];
        }
        __syncthreads();
        for (int t = tid; t < KK * KK; t += 256) Aout[(long)g * KK * KK + t] = sAn[t];
        if (tid < KK) {
            float d = 0.f;
#pragma unroll
            for (int c = 0; c < KK; c++) d += sAn[tid * KK + c];
            float nv = rsqrtf(fmaxf(d, 1.f));
            normOut[(long)g * KK + tid] = nv;
            snrm2[tid] = nv;
        }
    }
    __syncthreads();

    if (tid < KK) ssc[tid] = tanhf(ssc[tid]);
    __syncthreads();

    {
        int j = tid;
        float csum = 0.f, cmax = -3.402823466e38f;
#pragma unroll 4
        for (int r = 0; r < KK; r++) {
            int row = sidx[r];
            float v = Xg[(long)row * 256 + j] * ssc[r];
            csum += v;
            cmax = fmaxf(cmax, v);
            if (Xph) {
                float vs = v * snrm2[r];
                __nv_bfloat16 h = __float2bfloat16_rn(vs);
                long o = (long)g * KK * 256 + (long)r * 256 + j;
                Xph[o] = h;
                Xpl[o] = __float2bfloat16_rn(vs - __bfloat162float(h));
            }
        }
        readout[(long)g * 1536 + roff + j] = csum;
        readout[(long)g * 1536 + roff + 256 + j] = cmax;
    }
}

// ====== fused MLP head (round-7 proven) ========================================
__global__ void __launch_bounds__(256) mlp_head_kernel(
    const float* __restrict__ read, const float* __restrict__ Wd1,
    const float* __restrict__ bd1, const float* __restrict__ Wd2,
    const float* __restrict__ bd2, float* __restrict__ out)
{
    extern __shared__ float sm[];
    float* sR = sm;
    float* sP = sm + 4 * 1536;
    float* sH = sP;

    int tid = threadIdx.x;
    int g0 = blockIdx.x * 4;
    int lane = tid & 31, kw = tid >> 5;

    {
        const float4* src = (const float4*)(read + (long)g0 * 1536);
        float4* d4 = (float4*)sR;
#pragma unroll
        for (int i = 0; i < 6; i++) d4[tid + i * 256] = src[tid + i * 256];
    }
    __syncthreads();

    float4 acc[4];
#pragma unroll
    for (int gg = 0; gg < 4; gg++) acc[gg] = make_float4(0.f, 0.f, 0.f, 0.f);
    {
        const float4* W14 = (const float4*)Wd1;
        int kbeg = kw * 192;
#pragma unroll 2
        for (int k = kbeg; k < kbeg + 192; k++) {
            float4 wd = __ldg(&W14[k * 32 + lane]);
#pragma unroll
            for (int gg = 0; gg < 4; gg++) {
                float rv = sR[gg * 1536 + k];
                acc[gg].x += rv * wd.x;
                acc[gg].y += rv * wd.y;
                acc[gg].z += rv * wd.z;
                acc[gg].w += rv * wd.w;
            }
        }
    }
#pragma unroll
    for (int gg = 0; gg < 4; gg++)
        ((float4*)sP)[(kw * 4 + gg) * 32 + lane] = acc[gg];
    __syncthreads();

#pragma unroll
    for (int rep = 0; rep < 2; rep++) {
        int idx = tid + rep * 256;
        int gg = idx >> 7, j = idx & 127;
        float s = 0.f;
#pragma unroll
        for (int w = 0; w < 8; w++) s += sP[(w * 4 + gg) * 128 + j];
        s += bd1[j];
        s = (s > 0.f) ? s : 0.01f * s;
        acc[0].x = s;
        __syncthreads();
        sH[gg * 128 + j] = acc[0].x;
        __syncthreads();
    }

    if (kw < 4) {
        float a0 = 0.f, a1 = 0.f;
#pragma unroll
        for (int c = 0; c < 4; c++) {
            int k = lane + c * 32;
            float h = sH[kw * 128 + k];
            a0 += h * Wd2[k * 2 + 0];
            a1 += h * Wd2[k * 2 + 1];
        }
#pragma unroll
        for (int s = 16; s > 0; s >>= 1) {
            a0 += __shfl_down_sync(0xffffffffu, a0, s);
            a1 += __shfl_down_sync(0xffffffffu, a1, s);
        }
        if (lane == 0) {
            out[(g0 + kw) * 2 + 0] = 1.f / (1.f + expf(-(a0 + bd2[0])));
            out[(g0 + kw) * 2 + 1] = 1.f / (1.f + expf(-(a1 + bd2[1])));
        }
    }
}

// --------------------------------- launch --------------------------------------
extern "C" void kernel_launch(void* const* d_in, const int* in_sizes, int n_in,
                              void* d_out, int out_size)
{
    const float* feat = (const float*)d_in[0];
    const float* adj  = (const float*)d_in[1];
    const float* W0   = (const float*)d_in[2];
    const float* b0   = (const float*)d_in[3];
    const float* Ws0  = (const float*)d_in[4];
    const float* bs0  = (const float*)d_in[5];
    const float* W1   = (const float*)d_in[6];
    const float* b1   = (const float*)d_in[7];
    const float* Ws1  = (const float*)d_in[8];
    const float* bs1  = (const float*)d_in[9];
    const float* W2   = (const float*)d_in[10];
    const float* b2   = (const float*)d_in[11];
    const float* Ws2  = (const float*)d_in[12];
    const float* bs2  = (const float*)d_in[13];
    const float* Wd1  = (const float*)d_in[14];
    const float* bd1  = (const float*)d_in[15];
    const float* Wd2  = (const float*)d_in[16];
    const float* bd2  = (const float*)d_in[17];
    float* out = (float*)d_out;

    float *p_norm0, *p_X1, *p_spre, *p_A1, *p_norm1, *p_H1, *p_X2;
    float *p_A2, *p_norm2, *p_H2, *p_X3, *p_read;
    unsigned char* p_cols; int* p_cnt;
    __nv_bfloat16 *p_Yh, *p_Yl, *p_W0h, *p_W0l, *p_W1h, *p_W1l, *p_W2h, *p_W2l;
    __nv_bfloat16 *p_Xp1h, *p_Xp1l, *p_Xp2h, *p_Xp2l;
    cudaGetSymbolAddress((void**)&p_norm0, g_norm0);
    cudaGetSymbolAddress((void**)&p_cols, g_cols);
    cudaGetSymbolAddress((void**)&p_cnt, g_cnt);
    cudaGetSymbolAddress((void**)&p_Yh, g_Yh);
    cudaGetSymbolAddress((void**)&p_Yl, g_Yl);
    cudaGetSymbolAddress((void**)&p_W0h, g_W0h);
    cudaGetSymbolAddress((void**)&p_W0l, g_W0l);
    cudaGetSymbolAddress((void**)&p_W1h, g_W1h);
    cudaGetSymbolAddress((void**)&p_W1l, g_W1l);
    cudaGetSymbolAddress((void**)&p_W2h, g_W2h);
    cudaGetSymbolAddress((void**)&p_W2l, g_W2l);
    cudaGetSymbolAddress((void**)&p_X1, g_X1);
    cudaGetSymbolAddress((void**)&p_spre, g_spre);
    cudaGetSymbolAddress((void**)&p_Xp1h, g_Xp1h);
    cudaGetSymbolAddress((void**)&p_Xp1l, g_Xp1l);
    cudaGetSymbolAddress((void**)&p_A1, g_A1);
    cudaGetSymbolAddress((void**)&p_norm1, g_norm1);
    cudaGetSymbolAddress((void**)&p_H1, g_H1);
    cudaGetSymbolAddress((void**)&p_X2, g_X2);
    cudaGetSymbolAddress((void**)&p_Xp2h, g_Xp2h);
    cudaGetSymbolAddress((void**)&p_Xp2l, g_Xp2l);
    cudaGetSymbolAddress((void**)&p_A2, g_A2);
    cudaGetSymbolAddress((void**)&p_norm2, g_norm2);
    cudaGetSymbolAddress((void**)&p_H2, g_H2);
    cudaGetSymbolAddress((void**)&p_X3, g_X3);
    cudaGetSymbolAddress((void**)&p_read, g_read);

    const int headSmem = (4 * 1536 + 8 * 4 * 128) * 4;
    const int wmmaSmem = 2 * STG_B;   // 92160 B
    const int spmmSmem = 65536;
    cudaFuncSetAttribute(spmm_feat_kernel, cudaFuncAttributeMaxDynamicSharedMemorySize, spmmSmem);
    cudaFuncSetAttribute(mlp_head_kernel, cudaFuncAttributeMaxDynamicSharedMemorySize, headSmem);
    cudaFuncSetAttribute(wmma_gen_kernel<1>, cudaFuncAttributeMaxDynamicSharedMemorySize, wmmaSmem);
    cudaFuncSetAttribute(wmma_gen_kernel<0>, cudaFuncAttributeMaxDynamicSharedMemorySize, wmmaSmem);

    // ---- layer 0
    build_adj_kernel<<<G * NNODE / 8, 256>>>(adj, p_cols, p_cnt, p_norm0);
    split_all_w_kernel<<<640, 256>>>(W0, W1, W2, p_W0h, p_W0l, p_W1h, p_W1l,
                                     p_W2h, p_W2l);
    spmm_feat_kernel<<<dim3(2, G, 1), 256, spmmSmem>>>(p_cols, p_cnt, feat, p_norm0,
                                                       p_Yh, p_Yl);
    wmma_gen_kernel<1><<<dim3(2, 2048, 1), 256, wmmaSmem>>>(
        p_Yh, p_Yl, p_W0h, p_W0l, b0, Ws0, p_X1, p_spre, G * NNODE, FIN);
    pool_kernel<256, 32><<<G, 256>>>(p_X1, adj, p_norm0, Ws0, bs0, p_cols, p_cnt,
                                     p_spre, p_Xp1h, p_Xp1l, p_A1, p_norm1, p_read, 0);
    // ---- layer 1
    wmma_gen_kernel<0><<<dim3(2, 256, 1), 256, wmmaSmem>>>(
        p_Xp1h, p_Xp1l, p_W1h, p_W1l, nullptr, nullptr, p_H1, nullptr, G * 32, DH);
    conv_small_kernel<32><<<G, 256>>>(p_A1, p_H1, p_norm1, b1, p_X2);
    pool_kernel<32, 16><<<G, 256>>>(p_X2, p_A1, p_norm1, Ws1, bs1, nullptr, nullptr,
                                    nullptr, p_Xp2h, p_Xp2l, p_A2, p_norm2, p_read, 512);
    // ---- layer 2
    wmma_gen_kernel<0><<<dim3(2, 128, 1), 256, wmmaSmem>>>(
        p_Xp2h, p_Xp2l, p_W2h, p_W2l, nullptr, nullptr, p_H2, nullptr, G * 16, DH);
    conv_small_kernel<16><<<G, 256>>>(p_A2, p_H2, p_norm2, b2, p_X3);
    pool_kernel<16, 8><<<G, 256>>>(p_X3, p_A2, p_norm2, Ws2, bs2, nullptr, nullptr,
                                   nullptr, nullptr, nullptr, nullptr, nullptr, p_read, 1024);
    // ---- fused MLP head
    mlp_head_kernel<<<G / 4, 256, headSmem>>>(p_read, Wd1, bd1, Wd2, bd2, out);
}

// round 17
// speedup vs baseline: 1.0272x; 1.0184x over previous
#include <cuda_runtime.h>
#include <cuda_bf16.h>
#include <mma.h>
#include <math.h>

using namespace nvcuda;

#define G 1024
#define NNODE 256
#define FIN 128
#define DH 256
#define MAXD 128

// ---------------- scratch (device globals; no allocations allowed) -------------
__device__ float g_norm0[G * NNODE];
__device__ unsigned char g_cols[(long)G * NNODE * MAXD];
__device__ int   g_cnt [G * NNODE];
__device__ __nv_bfloat16 g_Yh[(long)G * NNODE * FIN];
__device__ __nv_bfloat16 g_Yl[(long)G * NNODE * FIN];
__device__ __nv_bfloat16 g_W0h[FIN * DH];
__device__ __nv_bfloat16 g_W0l[FIN * DH];
__device__ __nv_bfloat16 g_W1h[DH * DH];
__device__ __nv_bfloat16 g_W1l[DH * DH];
__device__ __nv_bfloat16 g_W2h[DH * DH];
__device__ __nv_bfloat16 g_W2l[DH * DH];
__device__ float g_X1 [G * NNODE * DH];
__device__ float g_spre[2 * G * NNODE];
__device__ __nv_bfloat16 g_Xp1h[(long)G * 32 * DH];
__device__ __nv_bfloat16 g_Xp1l[(long)G * 32 * DH];
__device__ float g_A1 [G * 32 * 32];
__device__ float g_norm1[G * 32];
__device__ float g_H1 [G * 32 * DH];
__device__ float g_X2 [G * 32 * DH];
__device__ __nv_bfloat16 g_Xp2h[(long)G * 16 * DH];
__device__ __nv_bfloat16 g_Xp2l[(long)G * 16 * DH];
__device__ float g_A2 [G * 16 * 16];
__device__ float g_norm2[G * 16];
__device__ float g_H2 [G * 16 * DH];
__device__ float g_X3 [G * 16 * DH];
__device__ float g_read[G * 1536];

// ---------------- cp.async helpers ---------------------------------------------
__device__ __forceinline__ void cp_async16(unsigned saddr, const void* gptr) {
    asm volatile("cp.async.cg.shared.global [%0], [%1], 16;" :: "r"(saddr), "l"(gptr));
}

// ---------------- build sparse adjacency lists + degree norm -------------------
__global__ void build_adj_kernel(const float* __restrict__ adj,
                                 unsigned char* __restrict__ cols,
                                 int* __restrict__ cnt, float* __restrict__ nrm)
{
    int row  = blockIdx.x * 8 + (threadIdx.x >> 5);
    int lane = threadIdx.x & 31;
    const float* a = adj + (long)row * 256;
    unsigned char* lst = cols + (long)row * MAXD;
    int base = 0;
#pragma unroll
    for (int c = 0; c < 8; c++) {
        float v = a[c * 32 + lane];
        unsigned m = __ballot_sync(0xffffffffu, v != 0.f);
        if (v != 0.f) {
            int pos = base + __popc(m & ((1u << lane) - 1));
            if (pos < MAXD) lst[pos] = (unsigned char)(c * 32 + lane);
        }
        base += __popc(m);
    }
    if (lane == 0) {
        cnt[row] = (base > MAXD) ? MAXD : base;
        nrm[row] = rsqrtf(fmaxf((float)base, 1.f));
    }
}

// ---------------- split W0+W1+W2 into bf16 hi/lo (one launch) ------------------
__global__ void split_all_w_kernel(const float* __restrict__ W0,
                                   const float* __restrict__ W1,
                                   const float* __restrict__ W2,
                                   __nv_bfloat16* __restrict__ W0h, __nv_bfloat16* __restrict__ W0l,
                                   __nv_bfloat16* __restrict__ W1h, __nv_bfloat16* __restrict__ W1l,
                                   __nv_bfloat16* __restrict__ W2h, __nv_bfloat16* __restrict__ W2l)
{
    int i = blockIdx.x * 256 + threadIdx.x;   // [0, 163840)
    const float* W; __nv_bfloat16 *Wh, *Wl; int idx;
    if (i < 32768)       { W = W0; Wh = W0h; Wl = W0l; idx = i; }
    else if (i < 98304)  { W = W1; Wh = W1h; Wl = W1l; idx = i - 32768; }
    else                 { W = W2; Wh = W2h; Wl = W2l; idx = i - 98304; }
    float v = W[idx];
    __nv_bfloat16 h = __float2bfloat16_rn(v);
    Wh[idx] = h;
    Wl[idx] = __float2bfloat16_rn(v - __bfloat162float(h));
}

// ------- layer-0 sparse aggregation, 64-col halves (2 CTA/SM); bf16 hi/lo out --
__global__ void spmm_feat_kernel(const unsigned char* __restrict__ cols,
                                 const int* __restrict__ cnt,
                                 const float* __restrict__ feat,
                                 const float* __restrict__ nrm,
                                 __nv_bfloat16* __restrict__ Yh,
                                 __nv_bfloat16* __restrict__ Yl)
{
    extern __shared__ float sX[];                 // [256][64] = 64 KB
    __shared__ float snrm[256];
    __shared__ int   scnt[256];

    int g = blockIdx.y, half = blockIdx.x;
    int tid = threadIdx.x;
    snrm[tid] = nrm[g * 256 + tid];
    scnt[tid] = cnt[g * 256 + tid];
    __syncthreads();

    {
        const float4* F = (const float4*)(feat + (long)g * 32768 + half * 64);
        float4* s4 = (float4*)sX;
        for (int t = tid; t < 4096; t += 256) {
            int r = t >> 4, c4 = t & 15;
            float4 v = F[(long)r * 32 + c4];
            float s = snrm[r];
            v.x *= s; v.y *= s; v.z *= s; v.w *= s;
            s4[r * 16 + c4] = v;
        }
    }
    __syncthreads();

    int lane = tid & 31, warp = tid >> 5;
    for (int i = warp; i < 256; i += 8) {
        int d = scnt[i];
        const unsigned char* lst = cols + ((long)g * 256 + i) * MAXD;
        float a0 = 0.f, a1 = 0.f;
        int k = 0;
        for (; k + 4 <= d; k += 4) {
            unsigned w = *(const unsigned*)(lst + k);   // warp-uniform -> broadcast
            int j0 = w & 255, j1 = (w >> 8) & 255, j2 = (w >> 16) & 255, j3 = w >> 24;
            float2 h0 = *(const float2*)(sX + j0 * 64 + lane * 2);
            float2 h1 = *(const float2*)(sX + j1 * 64 + lane * 2);
            float2 h2 = *(const float2*)(sX + j2 * 64 + lane * 2);
            float2 h3 = *(const float2*)(sX + j3 * 64 + lane * 2);
            a0 += h0.x + h1.x + h2.x + h3.x;
            a1 += h0.y + h1.y + h2.y + h3.y;
        }
        for (; k < d; k++) {
            int j = lst[k];
            float2 h = *(const float2*)(sX + j * 64 + lane * 2);
            a0 += h.x; a1 += h.y;
        }
        float nr = snrm[i];
        float o0 = a0 * nr, o1 = a1 * nr;
        __nv_bfloat16 h0 = __float2bfloat16_rn(o0);
        __nv_bfloat16 h1 = __float2bfloat16_rn(o1);
        long base = (long)g * 32768 + (long)i * 128 + half * 64 + lane * 2;
        *(__nv_bfloat162*)(Yh + base) = __nv_bfloat162(h0, h1);
        *(__nv_bfloat162*)(Yl + base) = __nv_bfloat162(
            __float2bfloat16_rn(o0 - __bfloat162float(h0)),
            __float2bfloat16_rn(o1 - __bfloat162float(h1)));
    }
}

// ===== generalized bf16 wmma 3-chain GEMM, cp.async double-buffered ============
// EPI=1: smem-staged epilogue (+bias, leaky, fused Wsp dot -> spreOut).
// EPI=0: accumulators stored DIRECTLY to global (no smem staging, no extra sync).
#define WAL 56
#define WBL 136
#define WCL 132
#define STG_B 46080
#define STG_E 23040

template <int EPI>
__global__ void __launch_bounds__(256, 2) wmma_gen_kernel(
    const __nv_bfloat16* __restrict__ Ah, const __nv_bfloat16* __restrict__ Al,
    const __nv_bfloat16* __restrict__ Bh, const __nv_bfloat16* __restrict__ Bl,
    const float* __restrict__ bias, const float* __restrict__ Wsp,
    float* __restrict__ C, float* __restrict__ spreOut, int M, int K)
{
    extern __shared__ char smem[];
    __nv_bfloat16* sb = (__nv_bfloat16*)smem;
    float* sC = (float*)smem;
    unsigned sb32 = (unsigned)__cvta_generic_to_shared(smem);

    int tid = threadIdx.x, warp = tid >> 5;
    int bm = blockIdx.y * 128, bn = blockIdx.x * 128;
    int wm = warp >> 2, wn = warp & 3;

    wmma::fragment<wmma::accumulator, 16, 16, 16, float> acc[4][2];
#pragma unroll
    for (int i = 0; i < 4; i++)
#pragma unroll
        for (int j = 0; j < 2; j++) wmma::fill_fragment(acc[i][j], 0.f);

    auto issue_tile = [&](int k0, int buf) {
        unsigned base = sb32 + buf * STG_B;
#pragma unroll
        for (int it = 0; it < 2; it++) {
            int idx = tid + it * 256;
            int r = idx >> 2, c8 = (idx & 3) * 8;
            long gofs = (long)(bm + r) * K + k0 + c8;
            unsigned aoff = (unsigned)(r * WAL + c8) * 2;
            cp_async16(base + aoff, Ah + gofs);
            cp_async16(base + 14336 + aoff, Al + gofs);
        }
#pragma unroll
        for (int it = 0; it < 2; it++) {
            int idx = tid + it * 256;
            int r = idx >> 4, c8 = (idx & 15) * 8;
            long gofs = (long)(k0 + r) * 256 + bn + c8;
            unsigned boff = (unsigned)(r * WBL + c8) * 2;
            cp_async16(base + 28672 + boff, Bh + gofs);
            cp_async16(base + 37376 + boff, Bl + gofs);
        }
        asm volatile("cp.async.commit_group;" ::: "memory");
    };

    int NT = K >> 5;
    issue_tile(0, 0);

    for (int k = 0; k < NT; k++) {
        if (k < NT - 1) {
            issue_tile((k + 1) * 32, (k + 1) & 1);
            asm volatile("cp.async.wait_group 1;" ::: "memory");
        } else {
            asm volatile("cp.async.wait_group 0;" ::: "memory");
        }
        __syncthreads();

        __nv_bfloat16* sAh = sb + (k & 1) * STG_E;
        __nv_bfloat16* sAl = sAh + 7168;
        __nv_bfloat16* sBh = sAh + 14336;
        __nv_bfloat16* sBl = sAh + 18688;

#pragma unroll
        for (int kk = 0; kk < 32; kk += 16) {
            wmma::fragment<wmma::matrix_b, 16, 16, 16, __nv_bfloat16, wmma::row_major> bh[2], bl[2];
#pragma unroll
            for (int j = 0; j < 2; j++) {
                wmma::load_matrix_sync(bh[j], sBh + kk * WBL + wn * 32 + j * 16, WBL);
                wmma::load_matrix_sync(bl[j], sBl + kk * WBL + wn * 32 + j * 16, WBL);
            }
#pragma unroll
            for (int i = 0; i < 4; i++) {
                wmma::fragment<wmma::matrix_a, 16, 16, 16, __nv_bfloat16, wmma::row_major> ah, al;
                wmma::load_matrix_sync(ah, sAh + (wm * 64 + i * 16) * WAL + kk, WAL);
                wmma::load_matrix_sync(al, sAl + (wm * 64 + i * 16) * WAL + kk, WAL);
#pragma unroll
                for (int j = 0; j < 2; j++) {
                    wmma::mma_sync(acc[i][j], ah, bh[j], acc[i][j]);
                    wmma::mma_sync(acc[i][j], ah, bl[j], acc[i][j]);
                    wmma::mma_sync(acc[i][j], al, bh[j], acc[i][j]);
                }
            }
        }
        __syncthreads();
    }

    if (EPI == 0) {
        // direct global store — no bias/activation needed; identical values.
#pragma unroll
        for (int i = 0; i < 4; i++)
#pragma unroll
            for (int j = 0; j < 2; j++)
                wmma::store_matrix_sync(
                    C + (long)(bm + wm * 64 + i * 16) * 256 + bn + wn * 32 + j * 16,
                    acc[i][j], 256, wmma::mem_row_major);
        return;
    }

    // EPI==1: stage C through smem — padded stride WCL
#pragma unroll
    for (int i = 0; i < 4; i++)
#pragma unroll
        for (int j = 0; j < 2; j++)
            wmma::store_matrix_sync(sC + (wm * 64 + i * 16) * WCL + wn * 32 + j * 16,
                                    acc[i][j], WCL, wmma::mem_row_major);
    __syncthreads();

    {
        int row = tid >> 1, half = tid & 1;
        int gRow = bm + row;
        float rd = 0.f;
        float* dst = C + (long)gRow * 256 + bn + half * 64;
#pragma unroll
        for (int c4 = 0; c4 < 16; c4++) {
            int col = half * 64 + c4 * 4;
            float4 v = *(float4*)(sC + row * WCL + col);
            float4 bv = *(const float4*)(bias + bn + col);
            v.x += bv.x; v.y += bv.y; v.z += bv.z; v.w += bv.w;
            v.x = (v.x > 0.f) ? v.x : 0.01f * v.x;
            v.y = (v.y > 0.f) ? v.y : 0.01f * v.y;
            v.z = (v.z > 0.f) ? v.z : 0.01f * v.z;
            v.w = (v.w > 0.f) ? v.w : 0.01f * v.w;
            float4 wv = *(const float4*)(Wsp + bn + col);
            rd += v.x * wv.x + v.y * wv.y + v.z * wv.z + v.w * wv.w;
            *(float4*)(dst + c4 * 4) = v;
        }
        rd += __shfl_xor_sync(0xffffffffu, rd, 1);
        if (half == 0) spreOut[(long)blockIdx.x * M + gRow] = rd;
    }
}

// ---------------- small batched conv: X = leaky(adj@H * norm + b) ---------------
template <int NN>
__global__ void conv_small_kernel(const float* __restrict__ A, const float* __restrict__ H,
                                  const float* __restrict__ nrm, const float* __restrict__ bias,
                                  float* __restrict__ X)
{
    int g = blockIdx.x;
    __shared__ float sAdj[NN][NN + 1];
    __shared__ float sH[NN][256];
    const float* Ag = A + (long)g * NN * NN;
    int tid = threadIdx.x;
    for (int t = tid; t < NN * NN; t += 256) sAdj[t / NN][t % NN] = Ag[t];
    {
        const float4* Hg4 = (const float4*)(H + (long)g * NN * 256);
        float4* s4 = (float4*)sH;
        for (int t = tid; t < NN * 64; t += 256) s4[t] = Hg4[t];
    }
    __syncthreads();
    int j = tid;
    float bj = bias[j];
#pragma unroll 4
    for (int i = 0; i < NN; i++) {
        float acc = 0.f;
#pragma unroll
        for (int k = 0; k < NN; k++) acc += sAdj[i][k] * sH[k][j];
        float v = acc * nrm[(long)g * NN + i] + bj;
        X[(long)g * NN * 256 + (long)i * 256 + j] = (v > 0.f) ? v : 0.01f * v;
    }
}

// ---------------- SAGPool: emits Xp as bf16 hi/lo with next norm folded --------
template <int NV, int KK>
__global__ void pool_kernel(const float* __restrict__ X, const float* __restrict__ A,
                            const float* __restrict__ nrm,
                            const float* __restrict__ Ws, const float* __restrict__ bs,
                            const unsigned char* __restrict__ colsL,
                            const int* __restrict__ cntL,
                            const float* __restrict__ spreParts,
                            __nv_bfloat16* __restrict__ Xph,
                            __nv_bfloat16* __restrict__ Xpl,
                            float* __restrict__ Aout,
                            float* __restrict__ normOut, float* __restrict__ readout,
                            int roff)
{
    int g = blockIdx.x;
    const float* Xg = X + (long)g * NV * 256;
    const float* Ag = A + (long)g * NV * NV;
    const float* ng = nrm + (long)g * NV;

    __shared__ float sWs[256];
    __shared__ float spre[NV];
    __shared__ float ssc[NV];
    __shared__ int   sidx[NV];
    __shared__ float sAn[KK * KK];
    __shared__ float snrm2[KK];

    int tid = threadIdx.x, lane = tid & 31, warp = tid >> 5;

    if (spreParts) {
        if (tid < NV)
            spre[tid] = (spreParts[(long)g * NV + tid] +
                         spreParts[(long)G * NNODE + (long)g * NV + tid]) * ng[tid];
        __syncthreads();
    } else {
        sWs[tid] = Ws[tid];
        __syncthreads();
        for (int r = warp; r < NV; r += 8) {
            float acc = 0.f;
            for (int q = lane; q < 256; q += 32) acc += Xg[(long)r * 256 + q] * sWs[q];
#pragma unroll
            for (int s = 16; s > 0; s >>= 1) acc += __shfl_down_sync(0xffffffffu, acc, s);
            if (lane == 0) spre[r] = ng[r] * acc;
        }
        __syncthreads();
    }

    float bsv = bs[0];
    if (colsL) {
        for (int r = warp; r < NV; r += 8) {
            int d = cntL[g * NV + r];
            const unsigned char* lst = colsL + ((long)g * NV + r) * MAXD;
            float acc = 0.f;
            for (int q = lane; q < d; q += 32) acc += spre[lst[q]];
#pragma unroll
            for (int s = 16; s > 0; s >>= 1) acc += __shfl_down_sync(0xffffffffu, acc, s);
            if (lane == 0) { ssc[r] = ng[r] * acc + bsv; sidx[r] = r; }
        }
    } else {
        for (int r = warp; r < NV; r += 8) {
            float acc = 0.f;
            for (int q = lane; q < NV; q += 32) acc += Ag[(long)r * NV + q] * spre[q];
#pragma unroll
            for (int s = 16; s > 0; s >>= 1) acc += __shfl_down_sync(0xffffffffu, acc, s);
            if (lane == 0) { ssc[r] = ng[r] * acc + bsv; sidx[r] = r; }
        }
    }
    __syncthreads();

    for (int ksz = 2; ksz <= NV; ksz <<= 1) {
        for (int j = ksz >> 1; j > 0; j >>= 1) {
            if (tid < NV) {
                int ixj = tid ^ j;
                if (ixj > tid) {
                    float s1 = ssc[tid], s2 = ssc[ixj];
                    int i1 = sidx[tid], i2 = sidx[ixj];
                    bool firstWorse = (s1 < s2) || (s1 == s2 && i1 > i2);
                    bool descRegion = ((tid & ksz) == 0);
                    bool doSwap = descRegion ? firstWorse : !firstWorse;
                    if (doSwap) {
                        ssc[tid] = s2; ssc[ixj] = s1;
                        sidx[tid] = i2; sidx[ixj] = i1;
                    }
                }
            }
            __syncthreads();
        }
    }

    if (Aout) {
        for (int t = tid; t < KK * KK; t += 256) {
            int r = t / KK, c = t % KK;
            sAn[t] = Ag[(long)sidx[r] * NV + sidx[c]];
        }
        __syncthreads();
        for (int t = tid; t < KK * KK; t += 256) Aout[(long)g * KK * KK + t] = sAn[t];
        if (tid < KK) {
            float d = 0.f;
#pragma unroll
            for (int c = 0; c < KK; c++) d += sAn[tid * KK + c];
            float nv = rsqrtf(fmaxf(d, 1.f));
            normOut[(long)g * KK + tid] = nv;
            snrm2[tid] = nv;
        }
    }
    __syncthreads();

    if (tid < KK) ssc[tid] = tanhf(ssc[tid]);
    __syncthreads();

    {
        int j = tid;
        float csum = 0.f, cmax = -3.402823466e38f;
#pragma unroll 4
        for (int r = 0; r < KK; r++) {
            int row = sidx[r];
            float v = Xg[(long)row * 256 + j] * ssc[r];
            csum += v;
            cmax = fmaxf(cmax, v);
            if (Xph) {
                float vs = v * snrm2[r];
                __nv_bfloat16 h = __float2bfloat16_rn(vs);
                long o = (long)g * KK * 256 + (long)r * 256 + j;
                Xph[o] = h;
                Xpl[o] = __float2bfloat16_rn(vs - __bfloat162float(h));
            }
        }
        readout[(long)g * 1536 + roff + j] = csum;
        readout[(long)g * 1536 + roff + 256 + j] = cmax;
    }
}

// ====== fused MLP head (round-7 proven) ========================================
__global__ void __launch_bounds__(256) mlp_head_kernel(
    const float* __restrict__ read, const float* __restrict__ Wd1,
    const float* __restrict__ bd1, const float* __restrict__ Wd2,
    const float* __restrict__ bd2, float* __restrict__ out)
{
    extern __shared__ float sm[];
    float* sR = sm;
    float* sP = sm + 4 * 1536;
    float* sH = sP;

    int tid = threadIdx.x;
    int g0 = blockIdx.x * 4;
    int lane = tid & 31, kw = tid >> 5;

    {
        const float4* src = (const float4*)(read + (long)g0 * 1536);
        float4* d4 = (float4*)sR;
#pragma unroll
        for (int i = 0; i < 6; i++) d4[tid + i * 256] = src[tid + i * 256];
    }
    __syncthreads();

    float4 acc[4];
#pragma unroll
    for (int gg = 0; gg < 4; gg++) acc[gg] = make_float4(0.f, 0.f, 0.f, 0.f);
    {
        const float4* W14 = (const float4*)Wd1;
        int kbeg = kw * 192;
#pragma unroll 2
        for (int k = kbeg; k < kbeg + 192; k++) {
            float4 wd = __ldg(&W14[k * 32 + lane]);
#pragma unroll
            for (int gg = 0; gg < 4; gg++) {
                float rv = sR[gg * 1536 + k];
                acc[gg].x += rv * wd.x;
                acc[gg].y += rv * wd.y;
                acc[gg].z += rv * wd.z;
                acc[gg].w += rv * wd.w;
            }
        }
    }
#pragma unroll
    for (int gg = 0; gg < 4; gg++)
        ((float4*)sP)[(kw * 4 + gg) * 32 + lane] = acc[gg];
    __syncthreads();

#pragma unroll
    for (int rep = 0; rep < 2; rep++) {
        int idx = tid + rep * 256;
        int gg = idx >> 7, j = idx & 127;
        float s = 0.f;
#pragma unroll
        for (int w = 0; w < 8; w++) s += sP[(w * 4 + gg) * 128 + j];
        s += bd1[j];
        s = (s > 0.f) ? s : 0.01f * s;
        acc[0].x = s;
        __syncthreads();
        sH[gg * 128 + j] = acc[0].x;
        __syncthreads();
    }

    if (kw < 4) {
        float a0 = 0.f, a1 = 0.f;
#pragma unroll
        for (int c = 0; c < 4; c++) {
            int k = lane + c * 32;
            float h = sH[kw * 128 + k];
            a0 += h * Wd2[k * 2 + 0];
            a1 += h * Wd2[k * 2 + 1];
        }
#pragma unroll
        for (int s = 16; s > 0; s >>= 1) {
            a0 += __shfl_down_sync(0xffffffffu, a0, s);
            a1 += __shfl_down_sync(0xffffffffu, a1, s);
        }
        if (lane == 0) {
            out[(g0 + kw) * 2 + 0] = 1.f / (1.f + expf(-(a0 + bd2[0])));
            out[(g0 + kw) * 2 + 1] = 1.f / (1.f + expf(-(a1 + bd2[1])));
        }
    }
}

// --------------------------------- launch --------------------------------------
extern "C" void kernel_launch(void* const* d_in, const int* in_sizes, int n_in,
                              void* d_out, int out_size)
{
    const float* feat = (const float*)d_in[0];
    const float* adj  = (const float*)d_in[1];
    const float* W0   = (const float*)d_in[2];
    const float* b0   = (const float*)d_in[3];
    const float* Ws0  = (const float*)d_in[4];
    const float* bs0  = (const float*)d_in[5];
    const float* W1   = (const float*)d_in[6];
    const float* b1   = (const float*)d_in[7];
    const float* Ws1  = (const float*)d_in[8];
    const float* bs1  = (const float*)d_in[9];
    const float* W2   = (const float*)d_in[10];
    const float* b2   = (const float*)d_in[11];
    const float* Ws2  = (const float*)d_in[12];
    const float* bs2  = (const float*)d_in[13];
    const float* Wd1  = (const float*)d_in[14];
    const float* bd1  = (const float*)d_in[15];
    const float* Wd2  = (const float*)d_in[16];
    const float* bd2  = (const float*)d_in[17];
    float* out = (float*)d_out;

    float *p_norm0, *p_X1, *p_spre, *p_A1, *p_norm1, *p_H1, *p_X2;
    float *p_A2, *p_norm2, *p_H2, *p_X3, *p_read;
    unsigned char* p_cols; int* p_cnt;
    __nv_bfloat16 *p_Yh, *p_Yl, *p_W0h, *p_W0l, *p_W1h, *p_W1l, *p_W2h, *p_W2l;
    __nv_bfloat16 *p_Xp1h, *p_Xp1l, *p_Xp2h, *p_Xp2l;
    cudaGetSymbolAddress((void**)&p_norm0, g_norm0);
    cudaGetSymbolAddress((void**)&p_cols, g_cols);
    cudaGetSymbolAddress((void**)&p_cnt, g_cnt);
    cudaGetSymbolAddress((void**)&p_Yh, g_Yh);
    cudaGetSymbolAddress((void**)&p_Yl, g_Yl);
    cudaGetSymbolAddress((void**)&p_W0h, g_W0h);
    cudaGetSymbolAddress((void**)&p_W0l, g_W0l);
    cudaGetSymbolAddress((void**)&p_W1h, g_W1h);
    cudaGetSymbolAddress((void**)&p_W1l, g_W1l);
    cudaGetSymbolAddress((void**)&p_W2h, g_W2h);
    cudaGetSymbolAddress((void**)&p_W2l, g_W2l);
    cudaGetSymbolAddress((void**)&p_X1, g_X1);
    cudaGetSymbolAddress((void**)&p_spre, g_spre);
    cudaGetSymbolAddress((void**)&p_Xp1h, g_Xp1h);
    cudaGetSymbolAddress((void**)&p_Xp1l, g_Xp1l);
    cudaGetSymbolAddress((void**)&p_A1, g_A1);
    cudaGetSymbolAddress((void**)&p_norm1, g_norm1);
    cudaGetSymbolAddress((void**)&p_H1, g_H1);
    cudaGetSymbolAddress((void**)&p_X2, g_X2);
    cudaGetSymbolAddress((void**)&p_Xp2h, g_Xp2h);
    cudaGetSymbolAddress((void**)&p_Xp2l, g_Xp2l);
    cudaGetSymbolAddress((void**)&p_A2, g_A2);
    cudaGetSymbolAddress((void**)&p_norm2, g_norm2);
    cudaGetSymbolAddress((void**)&p_H2, g_H2);
    cudaGetSymbolAddress((void**)&p_X3, g_X3);
    cudaGetSymbolAddress((void**)&p_read, g_read);

    const int headSmem = (4 * 1536 + 8 * 4 * 128) * 4;
    const int wmmaSmem = 2 * STG_B;   // 92160 B
    const int spmmSmem = 65536;
    cudaFuncSetAttribute(spmm_feat_kernel, cudaFuncAttributeMaxDynamicSharedMemorySize, spmmSmem);
    cudaFuncSetAttribute(mlp_head_kernel, cudaFuncAttributeMaxDynamicSharedMemorySize, headSmem);
    cudaFuncSetAttribute(wmma_gen_kernel<1>, cudaFuncAttributeMaxDynamicSharedMemorySize, wmmaSmem);
    cudaFuncSetAttribute(wmma_gen_kernel<0>, cudaFuncAttributeMaxDynamicSharedMemorySize, wmmaSmem);

    // ---- layer 0
    build_adj_kernel<<<G * NNODE / 8, 256>>>(adj, p_cols, p_cnt, p_norm0);
    split_all_w_kernel<<<640, 256>>>(W0, W1, W2, p_W0h, p_W0l, p_W1h, p_W1l,
                                     p_W2h, p_W2l);
    spmm_feat_kernel<<<dim3(2, G, 1), 256, spmmSmem>>>(p_cols, p_cnt, feat, p_norm0,
                                                       p_Yh, p_Yl);
    wmma_gen_kernel<1><<<dim3(2, 2048, 1), 256, wmmaSmem>>>(
        p_Yh, p_Yl, p_W0h, p_W0l, b0, Ws0, p_X1, p_spre, G * NNODE, FIN);
    pool_kernel<256, 32><<<G, 256>>>(p_X1, adj, p_norm0, Ws0, bs0, p_cols, p_cnt,
                                     p_spre, p_Xp1h, p_Xp1l, p_A1, p_norm1, p_read, 0);
    // ---- layer 1
    wmma_gen_kernel<0><<<dim3(2, 256, 1), 256, wmmaSmem>>>(
        p_Xp1h, p_Xp1l, p_W1h, p_W1l, nullptr, nullptr, p_H1, nullptr, G * 32, DH);
    conv_small_kernel<32><<<G, 256>>>(p_A1, p_H1, p_norm1, b1, p_X2);
    pool_kernel<32, 16><<<G, 256>>>(p_X2, p_A1, p_norm1, Ws1, bs1, nullptr, nullptr,
                                    nullptr, p_Xp2h, p_Xp2l, p_A2, p_norm2, p_read, 512);
    // ---- layer 2
    wmma_gen_kernel<0><<<dim3(2, 128, 1), 256, wmmaSmem>>>(
        p_Xp2h, p_Xp2l, p_W2h, p_W2l, nullptr, nullptr, p_H2, nullptr, G * 16, DH);
    conv_small_kernel<16><<<G, 256>>>(p_A2, p_H2, p_norm2, b2, p_X3);
    pool_kernel<16, 8><<<G, 256>>>(p_X3, p_A2, p_norm2, Ws2, bs2, nullptr, nullptr,
                                   nullptr, nullptr, nullptr, nullptr, nullptr, p_read, 1024);
    // ---- fused MLP head
    mlp_head_kernel<<<G / 4, 256, headSmem>>>(p_read, Wd1, bd1, Wd2, bd2, out);
}